// round 14
// baseline (speedup 1.0000x reference)
#include <cuda_runtime.h>
#include <cuda_bf16.h>
#include <cstdint>
#include <math.h>

// Problem constants
constexpr int B  = 8;
constexpr int L  = 2048;
constexpr int H  = 256;
constexpr int BL = B * L;
constexpr float L2E = 1.4426950408889634f;
constexpr int PAD = 40;   // halfs per smem row in k_proj (80B)

// Scratch (device globals; no allocation allowed)
__device__ float g_st[BL];                  // tanh(text@Wt^T+bt)@wa[:H]
__device__ float g_so[BL];                  // tanh(opinion@Wo^T)@wa[H:]
__device__ __nv_bfloat16 g_VTh[B * H * L];  // V^T bf16 hi: [b][h][j] (8 MB)
__device__ __nv_bfloat16 g_VTl[B * H * L];  // V^T bf16 lo: [b][h][j] (8 MB)

// ---- bf16 hi/lo split helpers ----
__device__ __forceinline__ void bf16_split(float x, unsigned short& h,
                                           unsigned short& l) {
    __nv_bfloat16 hb = __float2bfloat16(x);
    float hf = __bfloat162float(hb);
    __nv_bfloat16 lb = __float2bfloat16(x - hf);
    h = __bfloat16_as_ushort(hb);
    l = __bfloat16_as_ushort(lb);
}
__device__ __forceinline__ uint32_t pack2(unsigned short lo, unsigned short hi) {
    return (uint32_t)lo | ((uint32_t)hi << 16);
}
__device__ __forceinline__ float ex2(float x) {
    float r;
    asm("ex2.approx.f32 %0, %1;" : "=f"(r) : "f"(x));
    return r;
}
__device__ __forceinline__ uint32_t smem_u32(const void* p) {
    uint32_t a;
    asm("{ .reg .u64 t; cvta.to.shared.u64 t, %1; cvt.u32.u64 %0, t; }"
        : "=r"(a) : "l"(p));
    return a;
}

// ---- warp MMA: D(16x8,f32) += A(16x16,bf16,row) * B(16x8,bf16,col) ----
__device__ __forceinline__ void mma_bf16(float* c, const uint32_t* a,
                                         uint32_t b0, uint32_t b1) {
    asm volatile(
        "mma.sync.aligned.m16n8k16.row.col.f32.bf16.bf16.f32 "
        "{%0,%1,%2,%3}, {%4,%5,%6,%7}, {%8,%9}, {%0,%1,%2,%3};"
        : "+f"(c[0]), "+f"(c[1]), "+f"(c[2]), "+f"(c[3])
        : "r"(a[0]), "r"(a[1]), "r"(a[2]), "r"(a[3]), "r"(b0), "r"(b1));
}
__device__ __forceinline__ void ldsm_x4(uint32_t* r, uint32_t addr) {
    asm volatile("ldmatrix.sync.aligned.m8n8.x4.shared.b16 {%0,%1,%2,%3}, [%4];"
                 : "=r"(r[0]), "=r"(r[1]), "=r"(r[2]), "=r"(r[3])
                 : "r"(addr));
}

// ---------------------------------------------------------------------------
// Kernel VT: transpose + bf16-split opinion_features -> g_VTh/g_VTl [b][h][j]
// ---------------------------------------------------------------------------
__global__ __launch_bounds__(256)
void k_vt(const float* __restrict__ opin) {
    __shared__ float tile[64][33];
    const int b = blockIdx.z;
    const int j0 = blockIdx.x * 64;
    const int h0 = blockIdx.y * 32;
    const int tid = threadIdx.x;

#pragma unroll
    for (int it = tid; it < 512; it += 256) {
        int j = it >> 3, hq = (it & 7) * 4;
        float4 v = *(const float4*)&opin[((size_t)(b * L + j0 + j)) * H + h0 + hq];
        tile[j][hq + 0] = v.x; tile[j][hq + 1] = v.y;
        tile[j][hq + 2] = v.z; tile[j][hq + 3] = v.w;
    }
    __syncthreads();

    const int h = tid >> 3, jq = (tid & 7) * 8;
    uint32_t uh[4], ul[4];
#pragma unroll
    for (int k = 0; k < 8; k += 2) {
        unsigned short h0s, l0s, h1s, l1s;
        bf16_split(tile[jq + k][h], h0s, l0s);
        bf16_split(tile[jq + k + 1][h], h1s, l1s);
        uh[k / 2] = pack2(h0s, h1s);
        ul[k / 2] = pack2(l0s, l1s);
    }
    const size_t o = ((size_t)(b * H + h0 + h)) * L + j0 + jq;
    *(uint4*)&g_VTh[o] = *(uint4*)uh;
    *(uint4*)&g_VTl[o] = *(uint4*)ul;
}

// ---------------------------------------------------------------------------
// Kernel 1: st / so projections via bf16 tensor cores (3-term, f32 acc).
// CTA: 64 rows x N=256, 8 warps (2m x 4n), warp tile 32x64.
// ---------------------------------------------------------------------------
constexpr uint32_t PROJ_SMEM = (2 * 64 * PAD + 2 * 256 * PAD) * 2 + 64 * 4;

__global__ __launch_bounds__(256, 2)
void k_proj(const float* __restrict__ text, const float* __restrict__ opin,
            const float* __restrict__ Wt, const float* __restrict__ bt,
            const float* __restrict__ Wo, const float* __restrict__ wa) {
    extern __shared__ char smraw[];
    unsigned short* Xh = (unsigned short*)smraw;
    unsigned short* Xl = Xh + 64 * PAD;
    unsigned short* Wh = Xl + 64 * PAD;
    unsigned short* Wl = Wh + 256 * PAD;
    float* stp = (float*)(Wl + 256 * PAD);

    const bool isT = (blockIdx.y == 0);
    const float* X = isT ? text : opin;
    const float* W = isT ? Wt : Wo;
    const int row0 = blockIdx.x * 64;
    const int tid = threadIdx.x;
    const int warp = tid >> 5, lane = tid & 31;
    const int wm = warp & 1, wn = warp >> 1;
    const int g = lane >> 2, c4 = lane & 3;

    float acc[2][8][4];
#pragma unroll
    for (int mt = 0; mt < 2; mt++)
#pragma unroll
        for (int nt = 0; nt < 8; nt++)
#pragma unroll
            for (int e = 0; e < 4; e++) acc[mt][nt][e] = 0.0f;

    const int xi = tid >> 2, xk = (tid & 3) * 8;

    for (int kt = 0; kt < 8; kt++) {
        const int k0 = kt * 32;
        float4 xv0 = *(const float4*)&X[(size_t)(row0 + xi) * H + k0 + xk];
        float4 xv1 = *(const float4*)&X[(size_t)(row0 + xi) * H + k0 + xk + 4];
        float4 wv[8];
#pragma unroll
        for (int q = 0; q < 8; q++)
            wv[q] = *(const float4*)&W[(size_t)tid * H + k0 + 4 * q];

        __syncthreads();
        {
            float xf[8] = {xv0.x, xv0.y, xv0.z, xv0.w, xv1.x, xv1.y, xv1.z, xv1.w};
#pragma unroll
            for (int q = 0; q < 8; q += 2) {
                unsigned short h0s, l0s, h1s, l1s;
                bf16_split(xf[q], h0s, l0s);
                bf16_split(xf[q + 1], h1s, l1s);
                *(uint32_t*)&Xh[xi * PAD + xk + q] = pack2(h0s, h1s);
                *(uint32_t*)&Xl[xi * PAD + xk + q] = pack2(l0s, l1s);
            }
        }
#pragma unroll
        for (int q = 0; q < 8; q++) {
            float wf[4] = {wv[q].x, wv[q].y, wv[q].z, wv[q].w};
#pragma unroll
            for (int e = 0; e < 4; e += 2) {
                unsigned short h0s, l0s, h1s, l1s;
                bf16_split(wf[e], h0s, l0s);
                bf16_split(wf[e + 1], h1s, l1s);
                *(uint32_t*)&Wh[tid * PAD + 4 * q + e] = pack2(h0s, h1s);
                *(uint32_t*)&Wl[tid * PAD + 4 * q + e] = pack2(l0s, l1s);
            }
        }
        __syncthreads();

#pragma unroll
        for (int ks = 0; ks < 2; ks++) {
            const int kb = ks * 16;
            uint32_t aH[2][4], aL[2][4];
#pragma unroll
            for (int mt = 0; mt < 2; mt++) {
                int base = (wm * 32 + mt * 16 + g) * PAD + kb + 2 * c4;
                aH[mt][0] = *(uint32_t*)&Xh[base];
                aH[mt][1] = *(uint32_t*)&Xh[base + 8 * PAD];
                aH[mt][2] = *(uint32_t*)&Xh[base + 8];
                aH[mt][3] = *(uint32_t*)&Xh[base + 8 * PAD + 8];
                aL[mt][0] = *(uint32_t*)&Xl[base];
                aL[mt][1] = *(uint32_t*)&Xl[base + 8 * PAD];
                aL[mt][2] = *(uint32_t*)&Xl[base + 8];
                aL[mt][3] = *(uint32_t*)&Xl[base + 8 * PAD + 8];
            }
#pragma unroll
            for (int nt = 0; nt < 8; nt++) {
                int bb = (wn * 64 + nt * 8 + g) * PAD + kb + 2 * c4;
                uint32_t bH0 = *(uint32_t*)&Wh[bb], bH1 = *(uint32_t*)&Wh[bb + 8];
                uint32_t bL0 = *(uint32_t*)&Wl[bb], bL1 = *(uint32_t*)&Wl[bb + 8];
#pragma unroll
                for (int mt = 0; mt < 2; mt++) {
                    mma_bf16(acc[mt][nt], aH[mt], bH0, bH1);
                    mma_bf16(acc[mt][nt], aH[mt], bL0, bL1);
                    mma_bf16(acc[mt][nt], aL[mt], bH0, bH1);
                }
            }
        }
    }

    if (tid < 64) stp[tid] = 0.0f;
    __syncthreads();
    const int wo = isT ? 0 : H;
#pragma unroll
    for (int mt = 0; mt < 2; mt++) {
#pragma unroll
        for (int hr = 0; hr < 2; hr++) {
            float s = 0.0f;
#pragma unroll
            for (int nt = 0; nt < 8; nt++) {
#pragma unroll
                for (int e = 0; e < 2; e++) {
                    int col = wn * 64 + nt * 8 + 2 * c4 + e;
                    float tv = acc[mt][nt][hr * 2 + e];
                    if (isT) tv += bt[col];
                    s += tanhf(tv) * wa[wo + col];
                }
            }
            s += __shfl_xor_sync(0xffffffffu, s, 1);
            s += __shfl_xor_sync(0xffffffffu, s, 2);
            if (c4 == 0)
                atomicAdd(&stp[wm * 32 + mt * 16 + hr * 8 + g], s);
        }
    }
    __syncthreads();
    if (tid < 64) {
        float* dst = isT ? g_st : g_so;
        dst[row0 + tid] = stp[tid];
    }
}

// ---------------------------------------------------------------------------
// Kernel 2: fused PV + softmax-normalization via bf16 mma.sync (3-term).
// Block-contiguous smem layout: each 8x8 fragment matrix = one 128B block.
// Tile (128 rows x 32 k halfs) = 16 row-blocks x 4 k-blocks; block (rb,kb)
// at (rb*4+kb)*128; row r within block at (r&7)*16. ldmatrix lanes then read
// contiguous 512B (min wavefronts); producer STS conflict-free.
// CTA: 128 i x 128 h; full j range per CTA so l is a by-product.
// ---------------------------------------------------------------------------
constexpr uint32_t TILE_B   = 128 * 32 * 2;    // 8192
constexpr uint32_t OFF_PH   = 0;
constexpr uint32_t OFF_PL   = TILE_B;
constexpr uint32_t OFF_VH   = 2 * TILE_B;
constexpr uint32_t OFF_VL   = 3 * TILE_B;
constexpr uint32_t BUF_SZ   = 4 * TILE_B;      // 32768
constexpr uint32_t OFF_MSM  = 2 * BUF_SZ;      // 65536: float2[2048]
constexpr uint32_t OFF_RL   = OFF_MSM + 16384; // 81920: float[2048]
constexpr uint32_t OFF_STI  = OFF_RL + 8192;   // 90112: float[128]
constexpr uint32_t OFF_LS   = OFF_STI + 512;   // 90624: float[256]
constexpr uint32_t OFF_LINV = OFF_LS + 1024;   // 91648: float[128]
constexpr uint32_t PV_SMEM  = OFF_LINV + 512;  // 92160

__global__ __launch_bounds__(256, 2)
void k_pv(const int* __restrict__ pos, const float* __restrict__ ba,
          float* __restrict__ out) {
    extern __shared__ char smraw[];
    char* smc = smraw;
    const uint32_t sb = smem_u32(smraw);

    float2* msm  = (float2*)(smc + OFF_MSM);
    float*  rlut = (float*)(smc + OFF_RL);
    float*  stis = (float*)(smc + OFF_STI);
    float*  ls   = (float*)(smc + OFF_LS);
    float*  linv = (float*)(smc + OFF_LINV);

    const int cta = blockIdx.x;
    const int b = cta >> 5;
    const int i0 = ((cta & 31) >> 1) * 128;
    const int h0 = (cta & 1) * 128;
    const int tid = threadIdx.x;
    const int warp = tid >> 5, lane = tid & 31;
    const int wm = warp >> 1, wn = warp & 1;   // 4m x 2n
    const int g = lane >> 2, c4 = lane & 3;

    // prologue: per-batch j-tables + per-row st
    for (int j = tid; j < L; j += 256) {
        int p = pos[b * L + j];
        bool op = (p >= 19 && p <= 21) || (p >= 33 && p <= 35) ||
                  (p >= 41 && p <= 46);
        float mu = op ? 8.0f : 1.0f;
        float so = g_so[b * L + j];
        msm[j] = make_float2(mu, so * mu);
    }
    for (int d = tid; d < L; d += 256)
        rlut[d] = ((d == 0) ? 0.5f : 1.0f / log2f(2.0f + (float)d)) * L2E;
    if (tid < 128) stis[tid] = g_st[b * L + i0 + tid] + ba[0];
    __syncthreads();

    // producer mapping: row = tid&127 (P-row i and V-row h), 16 j's
    const int prow = tid & 127;
    const int pk0 = (tid >> 7) * 16;
    const int gi = i0 + prow;
    const float sti = stis[prow];
    const __nv_bfloat16* vhp = &g_VTh[(size_t)(b * H + h0 + prow) * L + pk0];
    const __nv_bfloat16* vlp = &g_VTl[(size_t)(b * H + h0 + prow) * L + pk0];
    // block-layout store offset for this thread's two 16B segments
    const uint32_t soff = ((prow >> 3) * 4 + (tid >> 7) * 2) * 128 +
                          (prow & 7) * 16;
    float lsum = 0.0f;

    // ldmatrix per-lane base offsets into block-contiguous tiles (bytes)
    const uint32_t base_A = ((lane >> 3) & 1) * 512 + ((lane >> 4) & 1) * 128 +
                            (lane & 7) * 16;
    const uint32_t base_B = ((lane >> 4) & 1) * 512 + ((lane >> 3) & 1) * 128 +
                            (lane & 7) * 16;

    float acc[2][8][4];
#pragma unroll
    for (int mt = 0; mt < 2; mt++)
#pragma unroll
        for (int nt = 0; nt < 8; nt++)
#pragma unroll
            for (int e = 0; e < 4; e++) acc[mt][nt][e] = 0.0f;

    auto produceP = [&](int ct) {
        char* bufc = smc + (ct & 1) * BUF_SZ;
        const int j0n = ct * 32;
        uint32_t hp[8], lp[8];
        float lacc = 0.0f;
#pragma unroll
        for (int q = 0; q < 16; q += 2) {
            int j = j0n + pk0 + q;
            float2 m0 = msm[j], m1 = msm[j + 1];
            float s0 = fmaf(sti, m0.x, m0.y) * rlut[abs(gi - j)];
            float s1 = fmaf(sti, m1.x, m1.y) * rlut[abs(gi - j - 1)];
            float p0 = ex2(s0), p1 = ex2(s1);
            lacc += p0 + p1;
            unsigned short h0s, l0s, h1s, l1s;
            bf16_split(p0, h0s, l0s);
            bf16_split(p1, h1s, l1s);
            hp[q / 2] = pack2(h0s, h1s);
            lp[q / 2] = pack2(l0s, l1s);
        }
        lsum += lacc;
        *(uint4*)(bufc + OFF_PH + soff) = *(uint4*)&hp[0];
        *(uint4*)(bufc + OFF_PH + soff + 128) = *(uint4*)&hp[4];
        *(uint4*)(bufc + OFF_PL + soff) = *(uint4*)&lp[0];
        *(uint4*)(bufc + OFF_PL + soff + 128) = *(uint4*)&lp[4];
    };
    auto storeV = [&](int ct, uint4 vh0, uint4 vh1, uint4 vl0, uint4 vl1) {
        char* bufc = smc + (ct & 1) * BUF_SZ;
        *(uint4*)(bufc + OFF_VH + soff) = vh0;
        *(uint4*)(bufc + OFF_VH + soff + 128) = vh1;
        *(uint4*)(bufc + OFF_VL + soff) = vl0;
        *(uint4*)(bufc + OFF_VL + soff + 128) = vl1;
    };
    auto mma_ks = [&](int tb, int ks) {
        const uint32_t base = sb + tb * BUF_SZ;
        const uint32_t kofs = ks * 256;
        uint32_t aH[2][4], aL[2][4];
#pragma unroll
        for (int mt = 0; mt < 2; mt++) {
            uint32_t ao = base_A + (wm * 4 + mt * 2) * 512 + kofs;
            ldsm_x4(aH[mt], base + OFF_PH + ao);
            ldsm_x4(aL[mt], base + OFF_PL + ao);
        }
#pragma unroll
        for (int ntp = 0; ntp < 4; ntp++) {
            uint32_t bo = base_B + (wn * 8 + ntp * 2) * 512 + kofs;
            uint32_t bh[4], bl[4];
            ldsm_x4(bh, base + OFF_VH + bo);
            ldsm_x4(bl, base + OFF_VL + bo);
#pragma unroll
            for (int s2 = 0; s2 < 2; s2++) {
                const int nt = ntp * 2 + s2;
#pragma unroll
                for (int mt = 0; mt < 2; mt++) {
                    mma_bf16(acc[mt][nt], aH[mt], bh[2 * s2], bh[2 * s2 + 1]);
                    mma_bf16(acc[mt][nt], aH[mt], bl[2 * s2], bl[2 * s2 + 1]);
                    mma_bf16(acc[mt][nt], aL[mt], bh[2 * s2], bh[2 * s2 + 1]);
                }
            }
        }
    };

    // produce chunk 0
    {
        uint4 vh0 = *(const uint4*)(vhp);
        uint4 vh1 = *(const uint4*)(vhp + 8);
        uint4 vl0 = *(const uint4*)(vlp);
        uint4 vl1 = *(const uint4*)(vlp + 8);
        storeV(0, vh0, vh1, vl0, vl1);
        produceP(0);
    }
    __syncthreads();

    for (int t = 0; t < L / 32; t++) {
        uint4 vh0, vh1, vl0, vl1;
        const bool more = (t < L / 32 - 1);
        if (more) {
            const __nv_bfloat16* ph = vhp + (t + 1) * 32;
            const __nv_bfloat16* pl = vlp + (t + 1) * 32;
            vh0 = *(const uint4*)(ph);
            vh1 = *(const uint4*)(ph + 8);
            vl0 = *(const uint4*)(pl);
            vl1 = *(const uint4*)(pl + 8);
        }
        mma_ks(t & 1, 0);
        if (more) {
            storeV(t + 1, vh0, vh1, vl0, vl1);
            produceP(t + 1);
        }
        mma_ks(t & 1, 1);
        __syncthreads();
    }

    // row-sum reduction -> 1/l  (rows: tid&127; halves tid<128 / tid>=128)
    ls[tid] = lsum;
    __syncthreads();
    if (tid < 128) linv[tid] = 1.0f / (ls[tid] + ls[tid + 128]);
    __syncthreads();

    // write output scaled by 1/l
#pragma unroll
    for (int mt = 0; mt < 2; mt++) {
        const int r0l = wm * 32 + mt * 16 + g;
        const float il0 = linv[r0l], il1 = linv[r0l + 8];
#pragma unroll
        for (int nt = 0; nt < 8; nt++) {
            int col = h0 + wn * 64 + nt * 8 + 2 * c4;
            float2 v0 = make_float2(acc[mt][nt][0] * il0, acc[mt][nt][1] * il0);
            float2 v1 = make_float2(acc[mt][nt][2] * il1, acc[mt][nt][3] * il1);
            *(float2*)&out[((size_t)(b * L + i0 + r0l)) * H + col] = v0;
            *(float2*)&out[((size_t)(b * L + i0 + r0l + 8)) * H + col] = v1;
        }
    }
}

// ---------------------------------------------------------------------------
// Launch. Input order: opinion_features, text_features, pos_ids,
// Wt, bt, Wo, wa, ba. Output: (B, L, H) float32.
// ---------------------------------------------------------------------------
extern "C" void kernel_launch(void* const* d_in, const int* in_sizes, int n_in,
                              void* d_out, int out_size) {
    const float* opin = (const float*)d_in[0];
    const float* text = (const float*)d_in[1];
    const int*   pos  = (const int*)d_in[2];
    const float* Wt   = (const float*)d_in[3];
    const float* bt   = (const float*)d_in[4];
    const float* Wo   = (const float*)d_in[5];
    const float* wa   = (const float*)d_in[6];
    const float* ba   = (const float*)d_in[7];
    float* out = (float*)d_out;

    static bool attr_done = false;
    if (!attr_done) {
        cudaFuncSetAttribute(k_proj, cudaFuncAttributeMaxDynamicSharedMemorySize,
                             PROJ_SMEM);
        cudaFuncSetAttribute(k_pv, cudaFuncAttributeMaxDynamicSharedMemorySize,
                             PV_SMEM);
        attr_done = true;
    }

    k_vt<<<dim3(L / 64, H / 32, B), 256>>>(opin);
    k_proj<<<dim3(BL / 64, 2), 256, PROJ_SMEM>>>(text, opin, Wt, bt, Wo, wa);
    k_pv<<<B * (L / 64), 256, PV_SMEM>>>(pos, ba, out);
}